// round 2
// baseline (speedup 1.0000x reference)
#include <cuda_runtime.h>
#include <math.h>

#define D   32
#define GMAX 64
#define NMAX 100000

// -------- device scratch (no allocation allowed) --------
__device__ __align__(16) float g_agg[NMAX * D];   // 12.8 MB scatter accumulator
__device__ unsigned g_max[3 * GMAX * D];          // per-layer segment-max (encoded)
__device__ float    g_Wf[5 * D * D];              // BN-folded weights: lin0,lin1,lin2,conv0,conv1
__device__ float    g_bf[5 * D];                  // BN-folded biases

// monotone float <-> uint mapping so atomicMax(unsigned) == float max
__device__ __forceinline__ unsigned fenc(float f) {
    unsigned u = __float_as_uint(f);
    return (u & 0x80000000u) ? ~u : (u | 0x80000000u);
}
__device__ __forceinline__ float fdec(unsigned k) {
    return __uint_as_float((k & 0x80000000u) ? (k ^ 0x80000000u) : ~k);
}
__device__ __forceinline__ float elu1(float h) { return h > 0.f ? h : expm1f(h); }

// -------- fold BN (inference stats) into W,b ; init max buffers --------
__global__ void prep_kernel(const float* __restrict__ linW,  const float* __restrict__ linb,
                            const float* __restrict__ ling,  const float* __restrict__ linbe,
                            const float* __restrict__ linm,  const float* __restrict__ linv,
                            const float* __restrict__ convW, const float* __restrict__ convb,
                            const float* __restrict__ convg, const float* __restrict__ convbe,
                            const float* __restrict__ convm, const float* __restrict__ convv) {
    int t = threadIdx.x;   // 1024 threads = D*D
    #pragma unroll
    for (int m = 0; m < 5; m++) {
        const float *W, *b, *g, *be, *mu, *va;
        if (m < 3) {
            int l = m;
            W = linW + l*D*D;  b = linb + l*D;  g = ling + l*D;
            be = linbe + l*D;  mu = linm + l*D; va = linv + l*D;
        } else {
            int l = m - 3;
            W = convW + l*D*D; b = convb + l*D; g = convg + l*D;
            be = convbe + l*D; mu = convm + l*D; va = convv + l*D;
        }
        int col = t & (D - 1);
        float sc = g[col] * rsqrtf(va[col] + 1e-5f);
        g_Wf[m*D*D + t] = W[t] * sc;
        if (t < D) g_bf[m*D + t] = (b[t] - mu[t]) * sc + be[t];
    }
    // encode(-inf) = ~0xFF800000 = 0x007FFFFF
    for (int i = t; i < 3*GMAX*D; i += blockDim.x) g_max[i] = 0x007FFFFFu;
}

// -------- zero the scatter accumulator --------
__global__ void zero_kernel(int n4) {
    int i = blockIdx.x * blockDim.x + threadIdx.x;
    if (i < n4) reinterpret_cast<float4*>(g_agg)[i] = make_float4(0.f, 0.f, 0.f, 0.f);
}

// -------- layer 0: z = ELU(BNfold(x@W0)); Z = lw0*z; segmax(raw z) --------
__global__ void l0_kernel(const float* __restrict__ x, const int* __restrict__ batch,
                          const float* __restrict__ lw, float* __restrict__ Zout, int N) {
    __shared__ float Ws[D*D];
    __shared__ float bs[D];
    int t = threadIdx.x;
    for (int i = t; i < D*D; i += 256) Ws[i] = g_Wf[i];
    if (t < D) bs[t] = g_bf[t];
    __syncthreads();

    int node = (blockIdx.x * 256 + t) >> 5;
    int lane = t & 31;
    if (node >= N) return;

    float xv = x[node*D + lane];
    float h = bs[lane];
    #pragma unroll
    for (int k = 0; k < D; k++)
        h = fmaf(__shfl_sync(0xffffffffu, xv, k), Ws[k*D + lane], h);
    float z = elu1(h);
    Zout[node*D + lane] = lw[0] * z;                    // Z accumulates scaled z
    int seg = batch[node];
    atomicMax(&g_max[seg*D + lane], fenc(z));           // layer0 max is over RAW z
}

// -------- edge scatter: agg[dst] += x[src]  (8 threads/edge, float4 atomics) --------
__global__ void scatter_kernel(const int* __restrict__ ei,
                               const float* __restrict__ x, int E) {
    int t = blockIdx.x * blockDim.x + threadIdx.x;
    if (t >= E * 8) return;
    int e = t >> 3;
    int c = t & 7;
    int s = ei[e];
    int d = ei[E + e];
    float4 v = reinterpret_cast<const float4*>(x)[(size_t)s * 8 + c];
    atomicAdd(reinterpret_cast<float4*>(&g_agg[(size_t)d * D + c * 4]), v);
}

// -------- fused: x' = ELU(BNfold((x+agg)@Wc)); z = lw*ELU(BNfold(x'@Wl));
//                 xout = x'; Z += z; segmax(z) --------
__global__ void conv_fused_kernel(const float* __restrict__ xin, float* __restrict__ xout,
                                  const int* __restrict__ batch,
                                  const float* __restrict__ lw, float* __restrict__ Zbuf,
                                  int N, int cm, int lm, int l) {
    __shared__ float Wc[D*D], Wl[D*D];
    __shared__ float bc[D], bl[D];
    int t = threadIdx.x;
    for (int i = t; i < D*D; i += 256) {
        Wc[i] = g_Wf[cm*D*D + i];
        Wl[i] = g_Wf[lm*D*D + i];
    }
    if (t < D) { bc[t] = g_bf[cm*D + t]; bl[t] = g_bf[lm*D + t]; }
    __syncthreads();

    int node = (blockIdx.x * 256 + t) >> 5;
    int lane = t & 31;
    if (node >= N) return;

    float xv = xin[node*D + lane] + g_agg[node*D + lane];
    float h = bc[lane];
    #pragma unroll
    for (int k = 0; k < D; k++)
        h = fmaf(__shfl_sync(0xffffffffu, xv, k), Wc[k*D + lane], h);
    float xn = elu1(h);
    xout[node*D + lane] = xn;

    float h2 = bl[lane];
    #pragma unroll
    for (int k = 0; k < D; k++)
        h2 = fmaf(__shfl_sync(0xffffffffu, xn, k), Wl[k*D + lane], h2);
    float z = lw[l] * elu1(h2);                         // layers>=1: z is scaled BEFORE max
    Zbuf[node*D + lane] += z;
    int seg = batch[node];
    atomicMax(&g_max[l*GMAX*D + seg*D + lane], fenc(z));
}

// -------- out = sum of the three per-layer segment maxes --------
__global__ void final_kernel(float* __restrict__ out) {
    int i = blockIdx.x * blockDim.x + threadIdx.x;
    if (i < GMAX*D)
        out[i] = fdec(g_max[i]) + fdec(g_max[GMAX*D + i]) + fdec(g_max[2*GMAX*D + i]);
}

extern "C" void kernel_launch(void* const* d_in, const int* in_sizes, int n_in,
                              void* d_out, int out_size) {
    const float* x      = (const float*)d_in[0];
    const int*   ei     = (const int*)d_in[1];      // int32: JAX default (x64 disabled)
    const int*   batch  = (const int*)d_in[2];      // int32
    const float* lw     = (const float*)d_in[3];
    const float* linW   = (const float*)d_in[4];
    const float* linb   = (const float*)d_in[5];
    const float* ling   = (const float*)d_in[6];
    const float* linbe  = (const float*)d_in[7];
    const float* linm   = (const float*)d_in[8];
    const float* linv   = (const float*)d_in[9];
    const float* convW  = (const float*)d_in[10];
    const float* convb  = (const float*)d_in[11];
    const float* convg  = (const float*)d_in[12];
    const float* convbe = (const float*)d_in[13];
    const float* convm  = (const float*)d_in[14];
    const float* convv  = (const float*)d_in[15];

    int N = in_sizes[0] / D;
    int E = in_sizes[1] / 2;

    float* out = (float*)d_out;            // [G*D]
    float* Z   = out + GMAX * D;           // [N*D]
    float* xb  = Z + (size_t)N * D;        // [N*D] working x buffer (also final x output)

    int node_blocks = (N * 32 + 255) / 256;
    int n4 = (N * D) / 4;
    int zero_blocks = (n4 + 255) / 256;
    int sc_blocks = (E * 8 + 255) / 256;

    prep_kernel<<<1, 1024>>>(linW, linb, ling, linbe, linm, linv,
                             convW, convb, convg, convbe, convm, convv);
    zero_kernel<<<zero_blocks, 256>>>(n4);
    l0_kernel<<<node_blocks, 256>>>(x, batch, lw, Z, N);

    // layer 1: agg over original x, then fused conv-MLP + lin-MLP
    scatter_kernel<<<sc_blocks, 256>>>(ei, x, E);
    conv_fused_kernel<<<node_blocks, 256>>>(x, xb, batch, lw, Z, N, /*cm=*/3, /*lm=*/1, /*l=*/1);

    // layer 2: agg over x1 (in xb), fused again (in-place x update is row-local)
    zero_kernel<<<zero_blocks, 256>>>(n4);
    scatter_kernel<<<sc_blocks, 256>>>(ei, xb, E);
    conv_fused_kernel<<<node_blocks, 256>>>(xb, xb, batch, lw, Z, N, /*cm=*/4, /*lm=*/2, /*l=*/2);

    final_kernel<<<(GMAX*D + 255) / 256, 256>>>(out);
}